// round 14
// baseline (speedup 1.0000x reference)
#include <cuda_runtime.h>
#include <cuda_bf16.h>
#include <math.h>
#include <float.h>

// Problem constants
#define BATCH 8192
#define NP    25      // 5x5 grid
#define NDICT 14
#define NSE   32
#define NCC   64
#define NE    256
#define NNZ   512
#define K1    400     // 16 ch * 25 pos (conv1 output)
#define K2    800     // 32 ch * 25 pos (conv2 output / linear input)

// ---------------- device scratch (no allocation allowed) ----------------
__device__ float g_PE[9 * NDICT * NCC];           // PE[k9][d][c]
__device__ float g_R1[NP * NP * NDICT * 16];      // R[p1][p2][d][o]
__device__ float g_R2[NP * NP * NDICT * 16];
__device__ float g_C1[NP * 16];                   // const for phi1 conv1 [p1*16+o]
__device__ float g_zn[NNZ * NE];
__device__ float g_A1[BATCH * K1];                // relu1 phi1, layout [b][p*16+o]
__device__ float g_A2[BATCH * K1];                // relu1 phi2
__device__ float g_B1[(size_t)BATCH * K2];        // relu2 phi1
__device__ float g_B2[(size_t)BATCH * K2];        // relu2 phi2
__device__ float g_U1[BATCH * NE];
__device__ float g_E2[BATCH * NE];
__device__ float g_coef[BATCH];
__device__ float g_scores[(size_t)BATCH * NNZ];
__device__ float g_G[(size_t)BATCH * NNZ];
__device__ int   g_zind[BATCH];

// ---------------- precompute kernels ----------------

// PE[k9][d][c] = sum_e conv_embed_w[c][e][kh][kw] * embn[d][e]
__global__ void k_PE(const float* __restrict__ cw, const float* __restrict__ tab) {
    __shared__ float se[NDICT * NSE];
    __shared__ float sc[NDICT];
    int tid = threadIdx.x;
    for (int i = tid; i < NDICT * NSE; i += 256) se[i] = tab[i];
    __syncthreads();
    if (tid < NDICT) {
        float s = 0.f;
        #pragma unroll
        for (int e = 0; e < NSE; e++) { float v = se[tid * NSE + e]; s += v * v; }
        sc[tid] = fminf(1.0f, 1.0f / (sqrtf(s) + 1e-7f));
    }
    __syncthreads();
    for (int i = tid; i < NDICT * NSE; i += 256) se[i] *= sc[i / NSE];
    __syncthreads();

    int idx = blockIdx.x * 256 + tid;
    if (idx >= 9 * NDICT * NCC) return;
    int c = idx % NCC;
    int d = (idx / NCC) % NDICT;
    int k9 = idx / (NCC * NDICT);
    int kh = k9 / 3, kw = k9 % 3;
    float acc = 0.f;
    #pragma unroll 8
    for (int e = 0; e < NSE; e++)
        acc += cw[((c * NSE + e) * 3 + kh) * 3 + kw] * se[d * NSE + e];
    g_PE[(k9 * NDICT + d) * NCC + c] = acc;
}

// R[p1][p2][d][o]: composed (embed-conv o conv1) response, both phis in one launch.
__global__ void __launch_bounds__(400) k_R(const float* __restrict__ W1a,
                                           const float* __restrict__ W1b) {
    __shared__ float sW[9216];     // [(c*9+j)*16 + o]
    __shared__ float sPE[9 * 64];  // [k9*64 + c]
    const float* W1 = blockIdx.y ? W1b : W1a;
    float* R = blockIdx.y ? g_R2 : g_R1;
    int p1 = blockIdx.x / NDICT, d = blockIdx.x % NDICT;
    int tid = threadIdx.x;
    for (int i = tid; i < 9216; i += 400) {
        int o = i / 576, r = i % 576;          // r = c*9+j
        sW[r * 16 + o] = W1[i];
    }
    for (int i = tid; i < 576; i += 400)
        sPE[i] = g_PE[((i / 64) * NDICT + d) * NCC + (i % 64)];
    __syncthreads();

    int p2 = tid >> 4, o = tid & 15;           // p2 < 25
    int h1 = p1 / 5, w1 = p1 % 5, h2 = p2 / 5, w2 = p2 % 5;
    float acc = 0.f;
    int mhlo = max(0, max(h1, h2) - 1), mhhi = min(4, min(h1, h2) + 1);
    int mwlo = max(0, max(w1, w2) - 1), mwhi = min(4, min(w1, w2) + 1);
    for (int mh = mhlo; mh <= mhhi; mh++)
        for (int mw = mwlo; mw <= mwhi; mw++) {
            int j  = (mh - h1 + 1) * 3 + (mw - w1 + 1);
            int k9 = (h2 - mh + 1) * 3 + (w2 - mw + 1);
            const float* pe = sPE + k9 * 64;
            const float* w  = sW + j * 16 + o;
            #pragma unroll
            for (int c = 0; c < 64; c++) acc += w[c * 144] * pe[c];
        }
    R[((p1 * NP + p2) * NDICT + d) * 16 + o] = acc;
}

// C1[p1*16+o] = b1[o] + sum_{m in N3(p1)} sum_c W1[o][c][m-p1+1] * cb[c]
__global__ void k_C1(const float* __restrict__ W1, const float* __restrict__ b1,
                     const float* __restrict__ cb) {
    int t = blockIdx.x * blockDim.x + threadIdx.x;
    if (t >= NP * 16) return;
    int o = t & 15, p1 = t >> 4;
    int h1 = p1 / 5, w1 = p1 % 5;
    float acc = b1[o];
    for (int mh = max(0, h1 - 1); mh <= min(4, h1 + 1); mh++)
        for (int mw = max(0, w1 - 1); mw <= min(4, w1 + 1); mw++) {
            int jh = mh - h1 + 1, jw = mw - w1 + 1;
            const float* w = W1 + o * NCC * 9 + jh * 3 + jw;
            #pragma unroll 8
            for (int c = 0; c < NCC; c++) acc += w[c * 9] * cb[c];
        }
    g_C1[p1 * 16 + o] = acc;
}

// L2-normalize z_vectors: one warp per row of 256.
__global__ void k_zn(const float* __restrict__ zv) {
    int row = blockIdx.x * 8 + (threadIdx.x >> 5);
    int lane = threadIdx.x & 31;
    const float* src = zv + row * NE;
    float v[8], s = 0.f;
    #pragma unroll
    for (int k = 0; k < 8; k++) { v[k] = src[lane + 32 * k]; s += v[k] * v[k]; }
    #pragma unroll
    for (int o = 16; o; o >>= 1) s += __shfl_xor_sync(0xffffffffu, s, o);
    float inv = 1.0f / sqrtf(s);
    #pragma unroll
    for (int k = 0; k < 8; k++) g_zn[row * NE + lane + 32 * k] = v[k] * inv;
}

// ---------------- main pipeline ----------------

// Stage 1: relu(conv1) via LUT gather. 16 batches/block, 800 threads.
__global__ void __launch_bounds__(800) k_stage1(const int* __restrict__ s,
                                                const int* __restrict__ sp,
                                                const float* __restrict__ b1_2) {
    __shared__ int ss[16][NP], ssp[16][NP];
    int b0 = blockIdx.x * 16;
    int tid = threadIdx.x;
    if (tid < 400) {
        int b = tid / NP, p = tid % NP;
        ss[b][p]  = s[(b0 + b) * NP + p];
        ssp[b][p] = sp[(b0 + b) * NP + p];
    }
    __syncthreads();
    int bl = tid / 50, rem = tid % 50;
    int p1 = rem >> 1, oh = rem & 1;
    int ob = oh * 8;
    int h1 = p1 / 5, w1 = p1 % 5;
    float4 a1a = *(const float4*)&g_C1[p1 * 16 + ob];
    float4 a1b = *(const float4*)&g_C1[p1 * 16 + ob + 4];
    float4 a2a = *(const float4*)&b1_2[ob];
    float4 a2b = *(const float4*)&b1_2[ob + 4];
    for (int h2 = max(0, h1 - 2); h2 <= min(4, h1 + 2); h2++)
        for (int w2 = max(0, w1 - 2); w2 <= min(4, w1 + 2); w2++) {
            int p2 = h2 * 5 + w2;
            int base = (p1 * NP + p2) * (NDICT * 16) + ob;
            int d = ss[bl][p2], dp = ssp[bl][p2];
            const float* r1p  = &g_R1[base + d * 16];
            const float* r2pp = &g_R2[base + dp * 16];
            const float* r2p  = &g_R2[base + d * 16];
            float4 r1a  = *(const float4*)(r1p);
            float4 r1b  = *(const float4*)(r1p + 4);
            float4 r2aa = *(const float4*)(r2pp);
            float4 r2ab = *(const float4*)(r2pp + 4);
            float4 r2ba = *(const float4*)(r2p);
            float4 r2bb = *(const float4*)(r2p + 4);
            a1a.x += r1a.x; a1a.y += r1a.y; a1a.z += r1a.z; a1a.w += r1a.w;
            a1b.x += r1b.x; a1b.y += r1b.y; a1b.z += r1b.z; a1b.w += r1b.w;
            a2a.x += r2aa.x - r2ba.x; a2a.y += r2aa.y - r2ba.y;
            a2a.z += r2aa.z - r2ba.z; a2a.w += r2aa.w - r2ba.w;
            a2b.x += r2ab.x - r2bb.x; a2b.y += r2ab.y - r2bb.y;
            a2b.z += r2ab.z - r2bb.z; a2b.w += r2ab.w - r2bb.w;
        }
    size_t off = (size_t)(b0 + bl) * K1 + p1 * 16 + ob;
    *(float4*)&g_A1[off] = make_float4(fmaxf(a1a.x, 0.f), fmaxf(a1a.y, 0.f),
                                       fmaxf(a1a.z, 0.f), fmaxf(a1a.w, 0.f));
    *(float4*)&g_A1[off + 4] = make_float4(fmaxf(a1b.x, 0.f), fmaxf(a1b.y, 0.f),
                                           fmaxf(a1b.z, 0.f), fmaxf(a1b.w, 0.f));
    *(float4*)&g_A2[off] = make_float4(fmaxf(a2a.x, 0.f), fmaxf(a2a.y, 0.f),
                                       fmaxf(a2a.z, 0.f), fmaxf(a2a.w, 0.f));
    *(float4*)&g_A2[off + 4] = make_float4(fmaxf(a2b.x, 0.f), fmaxf(a2b.y, 0.f),
                                           fmaxf(a2b.z, 0.f), fmaxf(a2b.w, 0.f));
}

// Stage 2: B800 = relu(conv2(A400) + b2). Both phis in one launch (blockIdx.y).
#define CPAD 12
__global__ void __launch_bounds__(200) k_conv2(
    const float* __restrict__ W2a, const float* __restrict__ b2a,
    const float* __restrict__ W2b, const float* __restrict__ b2b) {
    __shared__ float sA[16 * 7 * 7 * CPAD];
    __shared__ float sW[16 * 9 * 32];       // [o1*9+j][o2]
    int ph = blockIdx.y;
    const float* A  = ph ? g_A2 : g_A1;
    const float* W2 = ph ? W2b : W2a;
    const float* b2 = ph ? b2b : b2a;
    float* Bo = ph ? g_B2 : g_B1;
    int tid = threadIdx.x;
    int b0 = blockIdx.x * 8;

    for (int i = tid; i < 16 * 49 * CPAD; i += 200) sA[i] = 0.f;
    for (int i = tid; i < 4608; i += 200) {
        int o2 = i & 31, r = i >> 5;        // r = o1*9+j
        sW[i] = W2[o2 * 144 + r];
    }
    __syncthreads();
    for (int i = tid; i < 8 * K1; i += 200) {
        int b = i / K1, r = i % K1;
        int p = r >> 4, o1 = r & 15, h = p / 5, w = p % 5;
        sA[((o1 * 7 + h + 1) * 7 + (w + 1)) * CPAD + b] = A[(size_t)(b0 + b) * K1 + r];
    }
    __syncthreads();

    int pp = tid % 25, o2g = tid / 25;
    int hp = pp / 5, wp = pp % 5;
    float acc[4][8];
    #pragma unroll
    for (int q = 0; q < 4; q++)
        #pragma unroll
        for (int b = 0; b < 8; b++) acc[q][b] = 0.f;

    for (int o1 = 0; o1 < 16; o1++) {
        #pragma unroll
        for (int j = 0; j < 9; j++) {
            int kh = j / 3, kw = j % 3;
            float4 wv = *(const float4*)&sW[(o1 * 9 + j) * 32 + o2g * 4];
            int base = ((o1 * 7 + hp + kh) * 7 + (wp + kw)) * CPAD;
            float4 a0 = *(const float4*)&sA[base];
            float4 a1 = *(const float4*)&sA[base + 4];
            float a[8] = {a0.x, a0.y, a0.z, a0.w, a1.x, a1.y, a1.z, a1.w};
            float w[4] = {wv.x, wv.y, wv.z, wv.w};
            #pragma unroll
            for (int q = 0; q < 4; q++)
                #pragma unroll
                for (int b = 0; b < 8; b++) acc[q][b] += w[q] * a[b];
        }
    }

    #pragma unroll
    for (int q = 0; q < 4; q++) {
        int o2 = o2g * 4 + q;
        float bias = b2[o2];
        #pragma unroll
        for (int b = 0; b < 8; b++)
            Bo[(size_t)(b0 + b) * K2 + o2 * NP + pp] = fmaxf(acc[q][b] + bias, 0.f);
    }
}

// ---------------- 3xBF16 tensor-core NT GEMM ----------------
// C[M,N] = rowscale[m] * (A[M,K] . B[N,K]^T + bias[n])
// block 128x128, 8 warps (2x4) of 64x32, BK=16 (8 packed k2-slabs).
// fp32 operands split hi/lo bf16 at smem-store; 3 passes of m16n8k16
// (hi.lo + lo.hi + hi.hi) per tile -> ~1e-5 dot accuracy at bf16 MMA rate.
#define TBK 16
#define SPAD 136

__device__ __forceinline__ void bf16_split2(float x0, float x1,
                                            unsigned& hi, unsigned& lo) {
    __nv_bfloat162 h, l;
    h.x = __float2bfloat16(x0);
    h.y = __float2bfloat16(x1);
    l.x = __float2bfloat16(x0 - __bfloat162float(h.x));
    l.y = __float2bfloat16(x1 - __bfloat162float(h.y));
    hi = *(unsigned*)&h;
    lo = *(unsigned*)&l;
}

__device__ __forceinline__ void mma16(float* d, const unsigned* a, const unsigned* b) {
    asm volatile(
        "mma.sync.aligned.m16n8k16.row.col.f32.bf16.bf16.f32 "
        "{%0,%1,%2,%3}, {%4,%5,%6,%7}, {%8,%9}, {%0,%1,%2,%3};"
        : "+f"(d[0]), "+f"(d[1]), "+f"(d[2]), "+f"(d[3])
        : "r"(a[0]), "r"(a[1]), "r"(a[2]), "r"(a[3]), "r"(b[0]), "r"(b[1]));
}

__global__ void __launch_bounds__(256) k_bgemm(
    const float* __restrict__ A0, const float* __restrict__ A1src,
    const float* __restrict__ BB0, const float* __restrict__ BB1,
    const float* __restrict__ bias0, const float* __restrict__ bias1,
    const float* __restrict__ rs0, const float* __restrict__ rs1,
    float* __restrict__ C0, float* __restrict__ C1, int K, int N) {
    // packed bf16x2 planes: index [k2][row], k2 = k/2 in 0..7
    __shared__ unsigned sAhi[8][SPAD], sAlo[8][SPAD];
    __shared__ unsigned sBhi[8][SPAD], sBlo[8][SPAD];
    int z = blockIdx.z;
    const float* A = z ? A1src : A0;
    const float* B = z ? BB1 : BB0;
    const float* bias = z ? bias1 : bias0;
    const float* rowscale = z ? rs1 : rs0;
    float* C = z ? C1 : C0;

    int tid = threadIdx.x;
    int wid = tid >> 5, lane = tid & 31;
    int g = lane >> 2, t4 = lane & 3;
    int wm = wid >> 2, wn = wid & 3;
    int bm = blockIdx.y * 128, bn = blockIdx.x * 128;

    int lrow = tid >> 1, lk2 = (tid & 1) << 2;   // k2 base 0 or 4
    const float* Ap = A + (size_t)(bm + lrow) * K + lk2 * 2;
    const float* Bp = B + (size_t)(bn + lrow) * K + lk2 * 2;

    float acc[4][4][4];
    #pragma unroll
    for (int mt = 0; mt < 4; mt++)
        #pragma unroll
        for (int nt = 0; nt < 4; nt++)
            #pragma unroll
            for (int q = 0; q < 4; q++) acc[mt][nt][q] = 0.f;

    float4 na0, na1, nb0, nb1;
    na0 = *(const float4*)(Ap);
    na1 = *(const float4*)(Ap + 4);
    nb0 = *(const float4*)(Bp);
    nb1 = *(const float4*)(Bp + 4);
    {
        unsigned h, l;
        bf16_split2(na0.x, na0.y, h, l); sAhi[lk2 + 0][lrow] = h; sAlo[lk2 + 0][lrow] = l;
        bf16_split2(na0.z, na0.w, h, l); sAhi[lk2 + 1][lrow] = h; sAlo[lk2 + 1][lrow] = l;
        bf16_split2(na1.x, na1.y, h, l); sAhi[lk2 + 2][lrow] = h; sAlo[lk2 + 2][lrow] = l;
        bf16_split2(na1.z, na1.w, h, l); sAhi[lk2 + 3][lrow] = h; sAlo[lk2 + 3][lrow] = l;
        bf16_split2(nb0.x, nb0.y, h, l); sBhi[lk2 + 0][lrow] = h; sBlo[lk2 + 0][lrow] = l;
        bf16_split2(nb0.z, nb0.w, h, l); sBhi[lk2 + 1][lrow] = h; sBlo[lk2 + 1][lrow] = l;
        bf16_split2(nb1.x, nb1.y, h, l); sBhi[lk2 + 2][lrow] = h; sBlo[lk2 + 2][lrow] = l;
        bf16_split2(nb1.z, nb1.w, h, l); sBhi[lk2 + 3][lrow] = h; sBlo[lk2 + 3][lrow] = l;
    }
    __syncthreads();

    int nT = K / TBK;
    for (int t = 0; t < nT; t++) {
        if (t + 1 < nT) {
            const float* Ap2 = Ap + (t + 1) * TBK;
            const float* Bp2 = Bp + (t + 1) * TBK;
            na0 = *(const float4*)(Ap2);
            na1 = *(const float4*)(Ap2 + 4);
            nb0 = *(const float4*)(Bp2);
            nb1 = *(const float4*)(Bp2 + 4);
        }
        {
            unsigned ahi[4][4], alo[4][4], bhi[4][2], blo[4][2];
            #pragma unroll
            for (int mt = 0; mt < 4; mt++) {
                int mr = wm * 64 + mt * 16 + g;
                ahi[mt][0] = sAhi[t4][mr];
                ahi[mt][1] = sAhi[t4][mr + 8];
                ahi[mt][2] = sAhi[t4 + 4][mr];
                ahi[mt][3] = sAhi[t4 + 4][mr + 8];
                alo[mt][0] = sAlo[t4][mr];
                alo[mt][1] = sAlo[t4][mr + 8];
                alo[mt][2] = sAlo[t4 + 4][mr];
                alo[mt][3] = sAlo[t4 + 4][mr + 8];
            }
            #pragma unroll
            for (int nt = 0; nt < 4; nt++) {
                int nc = wn * 32 + nt * 8 + g;
                bhi[nt][0] = sBhi[t4][nc];
                bhi[nt][1] = sBhi[t4 + 4][nc];
                blo[nt][0] = sBlo[t4][nc];
                blo[nt][1] = sBlo[t4 + 4][nc];
            }
            #pragma unroll
            for (int mt = 0; mt < 4; mt++)
                #pragma unroll
                for (int nt = 0; nt < 4; nt++) {
                    mma16(acc[mt][nt], ahi[mt], blo[nt]);
                    mma16(acc[mt][nt], alo[mt], bhi[nt]);
                    mma16(acc[mt][nt], ahi[mt], bhi[nt]);
                }
        }
        if (t + 1 < nT) {
            __syncthreads();
            unsigned h, l;
            bf16_split2(na0.x, na0.y, h, l); sAhi[lk2 + 0][lrow] = h; sAlo[lk2 + 0][lrow] = l;
            bf16_split2(na0.z, na0.w, h, l); sAhi[lk2 + 1][lrow] = h; sAlo[lk2 + 1][lrow] = l;
            bf16_split2(na1.x, na1.y, h, l); sAhi[lk2 + 2][lrow] = h; sAlo[lk2 + 2][lrow] = l;
            bf16_split2(na1.z, na1.w, h, l); sAhi[lk2 + 3][lrow] = h; sAlo[lk2 + 3][lrow] = l;
            bf16_split2(nb0.x, nb0.y, h, l); sBhi[lk2 + 0][lrow] = h; sBlo[lk2 + 0][lrow] = l;
            bf16_split2(nb0.z, nb0.w, h, l); sBhi[lk2 + 1][lrow] = h; sBlo[lk2 + 1][lrow] = l;
            bf16_split2(nb1.x, nb1.y, h, l); sBhi[lk2 + 2][lrow] = h; sBlo[lk2 + 2][lrow] = l;
            bf16_split2(nb1.z, nb1.w, h, l); sBhi[lk2 + 3][lrow] = h; sBlo[lk2 + 3][lrow] = l;
            __syncthreads();
        }
    }

    // epilogue
    #pragma unroll
    for (int mt = 0; mt < 4; mt++) {
        int r0 = bm + wm * 64 + mt * 16 + g;
        float rsv0 = rowscale ? rowscale[r0] : 1.f;
        float rsv1 = rowscale ? rowscale[r0 + 8] : 1.f;
        #pragma unroll
        for (int nt = 0; nt < 4; nt++) {
            int c0 = bn + wn * 32 + nt * 8 + 2 * t4;
            float bv0 = bias ? bias[c0] : 0.f;
            float bv1 = bias ? bias[c0 + 1] : 0.f;
            float2 w0, w1;
            w0.x = (acc[mt][nt][0] + bv0) * rsv0;
            w0.y = (acc[mt][nt][1] + bv1) * rsv0;
            w1.x = (acc[mt][nt][2] + bv0) * rsv1;
            w1.y = (acc[mt][nt][3] + bv1) * rsv1;
            *(float2*)&C[(size_t)r0 * N + c0] = w0;
            *(float2*)&C[(size_t)(r0 + 8) * N + c0] = w1;
        }
    }
}

// coef[i] = exp(scale) / (||U1_i|| + 1e-4)
__global__ void k_coef(const float* __restrict__ scale) {
    int i = blockIdx.x * 8 + (threadIdx.x >> 5);
    int lane = threadIdx.x & 31;
    const float* u = g_U1 + (size_t)i * NE;
    float s = 0.f;
    #pragma unroll
    for (int k = 0; k < 8; k++) { float v = u[lane + 32 * k]; s += v * v; }
    #pragma unroll
    for (int o = 16; o; o >>= 1) s += __shfl_xor_sync(0xffffffffu, s, o);
    if (lane == 0) g_coef[i] = expf(scale[0]) / (sqrtf(s) + 1e-4f);
}

// argmax over 512 scores per row, first-occurrence tie-break.
__global__ void k_argmax() {
    int i = blockIdx.x * 8 + (threadIdx.x >> 5);
    int lane = threadIdx.x & 31;
    const float* r = g_scores + (size_t)i * NNZ;
    float best = -FLT_MAX; int bi = 0;
    for (int z = lane; z < NNZ; z += 32) {
        float v = r[z];
        if (v > best) { best = v; bi = z; }
    }
    #pragma unroll
    for (int off = 16; off; off >>= 1) {
        float ov = __shfl_down_sync(0xffffffffu, best, off);
        int   oi = __shfl_down_sync(0xffffffffu, bi, off);
        if (ov > best || (ov == best && oi < bi)) { best = ov; bi = oi; }
    }
    if (lane == 0) g_zind[i] = bi;
}

// out[i][j] = G[i][zind[j]]  (256 MB, float4 stores)
__global__ void k_out(float* __restrict__ out) {
    __shared__ float row[NNZ];
    __shared__ int zj[4096];
    int i = blockIdx.y;
    int jb = blockIdx.x * 4096;
    for (int t = threadIdx.x; t < NNZ; t += 256) row[t] = g_G[(size_t)i * NNZ + t];
    for (int t = threadIdx.x; t < 4096; t += 256) zj[t] = g_zind[jb + t];
    __syncthreads();
    float4* op = (float4*)(out + (size_t)i * BATCH + jb);
    #pragma unroll
    for (int k = 0; k < 4; k++) {
        int j4 = (k * 256 + threadIdx.x);
        int j = j4 * 4;
        float4 v;
        v.x = row[zj[j]]; v.y = row[zj[j + 1]];
        v.z = row[zj[j + 2]]; v.w = row[zj[j + 3]];
        op[j4] = v;
    }
}

// ---------------- launcher ----------------
extern "C" void kernel_launch(void* const* d_in, const int* in_sizes, int n_in,
                              void* d_out, int out_size) {
    const int*   s     = (const int*)d_in[0];
    const int*   sp    = (const int*)d_in[1];
    const float* tab   = (const float*)d_in[2];
    const float* cw    = (const float*)d_in[3];
    const float* cb    = (const float*)d_in[4];
    const float* w1a   = (const float*)d_in[5];
    const float* b1a   = (const float*)d_in[6];
    const float* w2a   = (const float*)d_in[7];
    const float* b2a   = (const float*)d_in[8];
    const float* lwa   = (const float*)d_in[9];
    const float* lba   = (const float*)d_in[10];
    const float* w1b   = (const float*)d_in[11];
    const float* b1b   = (const float*)d_in[12];
    const float* w2b   = (const float*)d_in[13];
    const float* b2b   = (const float*)d_in[14];
    const float* lwb   = (const float*)d_in[15];
    const float* lbb   = (const float*)d_in[16];
    const float* zv    = (const float*)d_in[17];
    const float* scale = (const float*)d_in[18];
    float* out = (float*)d_out;

    float *pB1, *pB2, *pU1, *pE2, *pzn, *pscores, *pG, *pcoef;
    cudaGetSymbolAddress((void**)&pB1, g_B1);
    cudaGetSymbolAddress((void**)&pB2, g_B2);
    cudaGetSymbolAddress((void**)&pU1, g_U1);
    cudaGetSymbolAddress((void**)&pE2, g_E2);
    cudaGetSymbolAddress((void**)&pzn, g_zn);
    cudaGetSymbolAddress((void**)&pscores, g_scores);
    cudaGetSymbolAddress((void**)&pG, g_G);
    cudaGetSymbolAddress((void**)&pcoef, g_coef);

    // 1: PE (embn fused)
    k_PE<<<32, 256>>>(cw, tab);
    // 2: R for both phis
    k_R<<<dim3(NP * NDICT, 2), 400>>>(w1a, w1b);
    // 3: C1
    k_C1<<<2, 256>>>(w1a, b1a, cb);
    // 4: stage1 (16 batches/block)
    k_stage1<<<BATCH / 16, 800>>>(s, sp, b1b);
    // 5: conv2 both phis
    k_conv2<<<dim3(BATCH / 8, 2), 200>>>(w2a, b2a, w2b, b2b);
    // 6: combined U1/E2 bgemm
    k_bgemm<<<dim3(NE / 128, BATCH / 128, 2), 256>>>(
        pB1, pB2, lwa, lwb, lba, lbb, nullptr, nullptr, pU1, pE2, K2, NE);
    // 7: zn
    k_zn<<<64, 256>>>(zv);
    // 8: coef
    k_coef<<<1024, 256>>>(scale);
    // 9: combined scores/G bgemm
    k_bgemm<<<dim3(NNZ / 128, BATCH / 128, 2), 256>>>(
        pE2, pU1, pzn, pzn, nullptr, nullptr, nullptr, pcoef,
        pscores, pG, NE, NNZ);
    // 10: argmax
    k_argmax<<<1024, 256>>>();
    // 11: gather-write output
    k_out<<<dim3(2, BATCH), 256>>>(out);
}

// round 17
// speedup vs baseline: 1.6312x; 1.6312x over previous
#include <cuda_runtime.h>
#include <cuda_bf16.h>
#include <math.h>
#include <float.h>

// Problem constants
#define BATCH 8192
#define NP    25      // 5x5 grid
#define NDICT 14
#define NSE   32
#define NCC   64
#define NE    256
#define NNZ   512
#define K1    400     // 16 ch * 25 pos (conv1 output)
#define K2    800     // 32 ch * 25 pos (conv2 output / linear input)

// ---------------- device scratch (no allocation allowed) ----------------
__device__ float g_PE[9 * NDICT * NCC];           // PE[k9][d][c]
__device__ float g_R1[NP * NP * NDICT * 16];      // R[p1][p2][d][o]
__device__ float g_R2[NP * NP * NDICT * 16];
__device__ float g_C1[NP * 16];                   // const for phi1 conv1 [p1*16+o]
__device__ float g_zn[NNZ * NE];
__device__ float g_A1[BATCH * K1];                // relu1 phi1, layout [b][p*16+o]
__device__ float g_A2[BATCH * K1];                // relu1 phi2
__device__ float g_B1[(size_t)BATCH * K2];        // relu2 phi1
__device__ float g_B2[(size_t)BATCH * K2];        // relu2 phi2
__device__ float g_U1[BATCH * NE];
__device__ float g_E2[BATCH * NE];
__device__ float g_coef[BATCH];
__device__ float g_scores[(size_t)BATCH * NNZ];
__device__ float g_G[(size_t)BATCH * NNZ];
__device__ int   g_zind[BATCH];

// ---------------- precompute kernels ----------------

// PE[k9][d][c] = sum_e conv_embed_w[c][e][kh][kw] * embn[d][e]
__global__ void k_PE(const float* __restrict__ cw, const float* __restrict__ tab) {
    __shared__ float se[NDICT * NSE];
    __shared__ float sc[NDICT];
    int tid = threadIdx.x;
    for (int i = tid; i < NDICT * NSE; i += 256) se[i] = tab[i];
    __syncthreads();
    if (tid < NDICT) {
        float s = 0.f;
        #pragma unroll
        for (int e = 0; e < NSE; e++) { float v = se[tid * NSE + e]; s += v * v; }
        sc[tid] = fminf(1.0f, 1.0f / (sqrtf(s) + 1e-7f));
    }
    __syncthreads();
    for (int i = tid; i < NDICT * NSE; i += 256) se[i] *= sc[i / NSE];
    __syncthreads();

    int idx = blockIdx.x * 256 + tid;
    if (idx >= 9 * NDICT * NCC) return;
    int c = idx % NCC;
    int d = (idx / NCC) % NDICT;
    int k9 = idx / (NCC * NDICT);
    int kh = k9 / 3, kw = k9 % 3;
    float acc = 0.f;
    #pragma unroll 8
    for (int e = 0; e < NSE; e++)
        acc += cw[((c * NSE + e) * 3 + kh) * 3 + kw] * se[d * NSE + e];
    g_PE[(k9 * NDICT + d) * NCC + c] = acc;
}

// R[p1][p2][d][o]: composed (embed-conv o conv1) response, both phis in one launch.
__global__ void __launch_bounds__(400) k_R(const float* __restrict__ W1a,
                                           const float* __restrict__ W1b) {
    __shared__ float sW[9216];     // [(c*9+j)*16 + o]
    __shared__ float sPE[9 * 64];  // [k9*64 + c]
    const float* W1 = blockIdx.y ? W1b : W1a;
    float* R = blockIdx.y ? g_R2 : g_R1;
    int p1 = blockIdx.x / NDICT, d = blockIdx.x % NDICT;
    int tid = threadIdx.x;
    for (int i = tid; i < 9216; i += 400) {
        int o = i / 576, r = i % 576;          // r = c*9+j
        sW[r * 16 + o] = W1[i];
    }
    for (int i = tid; i < 576; i += 400)
        sPE[i] = g_PE[((i / 64) * NDICT + d) * NCC + (i % 64)];
    __syncthreads();

    int p2 = tid >> 4, o = tid & 15;           // p2 < 25
    int h1 = p1 / 5, w1 = p1 % 5, h2 = p2 / 5, w2 = p2 % 5;
    float acc = 0.f;
    int mhlo = max(0, max(h1, h2) - 1), mhhi = min(4, min(h1, h2) + 1);
    int mwlo = max(0, max(w1, w2) - 1), mwhi = min(4, min(w1, w2) + 1);
    for (int mh = mhlo; mh <= mhhi; mh++)
        for (int mw = mwlo; mw <= mwhi; mw++) {
            int j  = (mh - h1 + 1) * 3 + (mw - w1 + 1);
            int k9 = (h2 - mh + 1) * 3 + (w2 - mw + 1);
            const float* pe = sPE + k9 * 64;
            const float* w  = sW + j * 16 + o;
            #pragma unroll
            for (int c = 0; c < 64; c++) acc += w[c * 144] * pe[c];
        }
    R[((p1 * NP + p2) * NDICT + d) * 16 + o] = acc;
}

// C1[p1*16+o] = b1[o] + sum_{m in N3(p1)} sum_c W1[o][c][m-p1+1] * cb[c]
__global__ void k_C1(const float* __restrict__ W1, const float* __restrict__ b1,
                     const float* __restrict__ cb) {
    int t = blockIdx.x * blockDim.x + threadIdx.x;
    if (t >= NP * 16) return;
    int o = t & 15, p1 = t >> 4;
    int h1 = p1 / 5, w1 = p1 % 5;
    float acc = b1[o];
    for (int mh = max(0, h1 - 1); mh <= min(4, h1 + 1); mh++)
        for (int mw = max(0, w1 - 1); mw <= min(4, w1 + 1); mw++) {
            int jh = mh - h1 + 1, jw = mw - w1 + 1;
            const float* w = W1 + o * NCC * 9 + jh * 3 + jw;
            #pragma unroll 8
            for (int c = 0; c < NCC; c++) acc += w[c * 9] * cb[c];
        }
    g_C1[p1 * 16 + o] = acc;
}

// L2-normalize z_vectors: one warp per row of 256.
__global__ void k_zn(const float* __restrict__ zv) {
    int row = blockIdx.x * 8 + (threadIdx.x >> 5);
    int lane = threadIdx.x & 31;
    const float* src = zv + row * NE;
    float v[8], s = 0.f;
    #pragma unroll
    for (int k = 0; k < 8; k++) { v[k] = src[lane + 32 * k]; s += v[k] * v[k]; }
    #pragma unroll
    for (int o = 16; o; o >>= 1) s += __shfl_xor_sync(0xffffffffu, s, o);
    float inv = 1.0f / sqrtf(s);
    #pragma unroll
    for (int k = 0; k < 8; k++) g_zn[row * NE + lane + 32 * k] = v[k] * inv;
}

// ---------------- main pipeline ----------------

// Stage 1: relu(conv1) via LUT gather, float4 per thread, 8 batches/block.
// (Measured-good 64.5us version.)
__global__ void __launch_bounds__(800) k_stage1(const int* __restrict__ s,
                                                const int* __restrict__ sp,
                                                const float* __restrict__ b1_2) {
    __shared__ int ss[8][NP], ssp[8][NP];
    int b0 = blockIdx.x * 8;
    int tid = threadIdx.x;
    if (tid < 200) {
        int b = tid / NP, p = tid % NP;
        ss[b][p]  = s[(b0 + b) * NP + p];
        ssp[b][p] = sp[(b0 + b) * NP + p];
    }
    __syncthreads();
    int bl = tid / 100, rem = tid % 100;
    int p1 = rem >> 2, og = rem & 3;
    int h1 = p1 / 5, w1 = p1 % 5;
    float4 a1 = *(const float4*)&g_C1[p1 * 16 + og * 4];
    float4 a2 = *(const float4*)&b1_2[og * 4];
    for (int h2 = max(0, h1 - 2); h2 <= min(4, h1 + 2); h2++)
        for (int w2 = max(0, w1 - 2); w2 <= min(4, w1 + 2); w2++) {
            int p2 = h2 * 5 + w2;
            int base = (p1 * NP + p2) * (NDICT * 16) + og * 4;
            int d = ss[bl][p2], dp = ssp[bl][p2];
            float4 r1  = *(const float4*)&g_R1[base + d * 16];
            float4 r2a = *(const float4*)&g_R2[base + dp * 16];
            float4 r2b = *(const float4*)&g_R2[base + d * 16];
            a1.x += r1.x; a1.y += r1.y; a1.z += r1.z; a1.w += r1.w;
            a2.x += r2a.x - r2b.x; a2.y += r2a.y - r2b.y;
            a2.z += r2a.z - r2b.z; a2.w += r2a.w - r2b.w;
        }
    float4 o1 = make_float4(fmaxf(a1.x, 0.f), fmaxf(a1.y, 0.f),
                            fmaxf(a1.z, 0.f), fmaxf(a1.w, 0.f));
    float4 o2 = make_float4(fmaxf(a2.x, 0.f), fmaxf(a2.y, 0.f),
                            fmaxf(a2.z, 0.f), fmaxf(a2.w, 0.f));
    size_t off = (size_t)(b0 + bl) * K1 + p1 * 16 + og * 4;
    *(float4*)&g_A1[off] = o1;
    *(float4*)&g_A2[off] = o2;
}

// Stage 2: B800 = relu(conv2(A400) + b2). Both phis in one launch (blockIdx.y).
#define CPAD 12
__global__ void __launch_bounds__(200) k_conv2(
    const float* __restrict__ W2a, const float* __restrict__ b2a,
    const float* __restrict__ W2b, const float* __restrict__ b2b) {
    __shared__ float sA[16 * 7 * 7 * CPAD];
    __shared__ float sW[16 * 9 * 32];       // [o1*9+j][o2]
    int ph = blockIdx.y;
    const float* A  = ph ? g_A2 : g_A1;
    const float* W2 = ph ? W2b : W2a;
    const float* b2 = ph ? b2b : b2a;
    float* Bo = ph ? g_B2 : g_B1;
    int tid = threadIdx.x;
    int b0 = blockIdx.x * 8;

    for (int i = tid; i < 16 * 49 * CPAD; i += 200) sA[i] = 0.f;
    for (int i = tid; i < 4608; i += 200) {
        int o2 = i & 31, r = i >> 5;        // r = o1*9+j
        sW[i] = W2[o2 * 144 + r];
    }
    __syncthreads();
    for (int i = tid; i < 8 * K1; i += 200) {
        int b = i / K1, r = i % K1;
        int p = r >> 4, o1 = r & 15, h = p / 5, w = p % 5;
        sA[((o1 * 7 + h + 1) * 7 + (w + 1)) * CPAD + b] = A[(size_t)(b0 + b) * K1 + r];
    }
    __syncthreads();

    int pp = tid % 25, o2g = tid / 25;
    int hp = pp / 5, wp = pp % 5;
    float acc[4][8];
    #pragma unroll
    for (int q = 0; q < 4; q++)
        #pragma unroll
        for (int b = 0; b < 8; b++) acc[q][b] = 0.f;

    for (int o1 = 0; o1 < 16; o1++) {
        #pragma unroll
        for (int j = 0; j < 9; j++) {
            int kh = j / 3, kw = j % 3;
            float4 wv = *(const float4*)&sW[(o1 * 9 + j) * 32 + o2g * 4];
            int base = ((o1 * 7 + hp + kh) * 7 + (wp + kw)) * CPAD;
            float4 a0 = *(const float4*)&sA[base];
            float4 a1 = *(const float4*)&sA[base + 4];
            float a[8] = {a0.x, a0.y, a0.z, a0.w, a1.x, a1.y, a1.z, a1.w};
            float w[4] = {wv.x, wv.y, wv.z, wv.w};
            #pragma unroll
            for (int q = 0; q < 4; q++)
                #pragma unroll
                for (int b = 0; b < 8; b++) acc[q][b] += w[q] * a[b];
        }
    }

    #pragma unroll
    for (int q = 0; q < 4; q++) {
        int o2 = o2g * 4 + q;
        float bias = b2[o2];
        #pragma unroll
        for (int b = 0; b < 8; b++)
            Bo[(size_t)(b0 + b) * K2 + o2 * NP + pp] = fmaxf(acc[q][b] + bias, 0.f);
    }
}

// ---------------- 3xBF16 tensor-core NT GEMM, low-pressure tile ----------------
// C[M,N] = rowscale[m] * (A[M,K] . B[N,K]^T + bias[n])
// block tile 128x64, 8 warps (2x4) of 64x16, BK=16, pre-split bf16 hi/lo
// planes, double-buffered (one sync per tile). ~115 regs/thread -> no spills.
#define SPAD 136
#define BPAD 72

__device__ __forceinline__ void bf16_split2(float x0, float x1,
                                            unsigned& hi, unsigned& lo) {
    __nv_bfloat162 h, l;
    h.x = __float2bfloat16(x0);
    h.y = __float2bfloat16(x1);
    l.x = __float2bfloat16(x0 - __bfloat162float(h.x));
    l.y = __float2bfloat16(x1 - __bfloat162float(h.y));
    hi = *(unsigned*)&h;
    lo = *(unsigned*)&l;
}

__device__ __forceinline__ void mma16(float* d, const unsigned* a, const unsigned* b) {
    asm volatile(
        "mma.sync.aligned.m16n8k16.row.col.f32.bf16.bf16.f32 "
        "{%0,%1,%2,%3}, {%4,%5,%6,%7}, {%8,%9}, {%0,%1,%2,%3};"
        : "+f"(d[0]), "+f"(d[1]), "+f"(d[2]), "+f"(d[3])
        : "r"(a[0]), "r"(a[1]), "r"(a[2]), "r"(a[3]), "r"(b[0]), "r"(b[1]));
}

__global__ void __launch_bounds__(256) k_bgemm(
    const float* __restrict__ A0, const float* __restrict__ A1src,
    const float* __restrict__ BB0, const float* __restrict__ BB1,
    const float* __restrict__ bias0, const float* __restrict__ bias1,
    const float* __restrict__ rs0, const float* __restrict__ rs1,
    float* __restrict__ C0, float* __restrict__ C1, int K, int N) {
    __shared__ unsigned sAhi[2][8][SPAD], sAlo[2][8][SPAD];
    __shared__ unsigned sBhi[2][8][BPAD], sBlo[2][8][BPAD];
    int z = blockIdx.z;
    const float* A = z ? A1src : A0;
    const float* B = z ? BB1 : BB0;
    const float* bias = z ? bias1 : bias0;
    const float* rowscale = z ? rs1 : rs0;
    float* C = z ? C1 : C0;

    int tid = threadIdx.x;
    int wid = tid >> 5, lane = tid & 31;
    int g = lane >> 2, t4 = lane & 3;
    int wm = wid >> 2, wn = wid & 3;        // warp: rows 64*wm, cols 16*wn
    int bm = blockIdx.y * 128, bn = blockIdx.x * 64;

    // loaders: A rows via (tid>>1), 8 floats; B rows via (tid>>2), 4 floats
    int lrow = tid >> 1, lk2 = (tid & 1) << 2;
    int brow = tid >> 2, bk2 = (tid & 3) << 1;
    const float* Ap = A + (size_t)(bm + lrow) * K + lk2 * 2;
    const float* Bp = B + (size_t)(bn + brow) * K + bk2 * 2;

    float acc[4][2][4];
    #pragma unroll
    for (int mt = 0; mt < 4; mt++)
        #pragma unroll
        for (int nt = 0; nt < 2; nt++)
            #pragma unroll
            for (int q = 0; q < 4; q++) acc[mt][nt][q] = 0.f;

    float4 na0, na1, nb0;
    na0 = *(const float4*)(Ap);
    na1 = *(const float4*)(Ap + 4);
    nb0 = *(const float4*)(Bp);
    {
        unsigned h, l;
        bf16_split2(na0.x, na0.y, h, l); sAhi[0][lk2 + 0][lrow] = h; sAlo[0][lk2 + 0][lrow] = l;
        bf16_split2(na0.z, na0.w, h, l); sAhi[0][lk2 + 1][lrow] = h; sAlo[0][lk2 + 1][lrow] = l;
        bf16_split2(na1.x, na1.y, h, l); sAhi[0][lk2 + 2][lrow] = h; sAlo[0][lk2 + 2][lrow] = l;
        bf16_split2(na1.z, na1.w, h, l); sAhi[0][lk2 + 3][lrow] = h; sAlo[0][lk2 + 3][lrow] = l;
        bf16_split2(nb0.x, nb0.y, h, l); sBhi[0][bk2 + 0][brow] = h; sBlo[0][bk2 + 0][brow] = l;
        bf16_split2(nb0.z, nb0.w, h, l); sBhi[0][bk2 + 1][brow] = h; sBlo[0][bk2 + 1][brow] = l;
    }
    __syncthreads();

    int nT = K / 16;
    int cur = 0;
    for (int t = 0; t < nT; t++) {
        if (t + 1 < nT) {
            const float* Ap2 = Ap + (t + 1) * 16;
            const float* Bp2 = Bp + (t + 1) * 16;
            na0 = *(const float4*)(Ap2);
            na1 = *(const float4*)(Ap2 + 4);
            nb0 = *(const float4*)(Bp2);
        }
        {
            unsigned bhi[2][2], blo[2][2];
            #pragma unroll
            for (int nt = 0; nt < 2; nt++) {
                int nc = wn * 16 + nt * 8 + g;
                bhi[nt][0] = sBhi[cur][t4][nc];
                bhi[nt][1] = sBhi[cur][t4 + 4][nc];
                blo[nt][0] = sBlo[cur][t4][nc];
                blo[nt][1] = sBlo[cur][t4 + 4][nc];
            }
            #pragma unroll
            for (int mt = 0; mt < 4; mt++) {
                int mr = wm * 64 + mt * 16 + g;
                unsigned ahi[4], alo[4];
                ahi[0] = sAhi[cur][t4][mr];
                ahi[1] = sAhi[cur][t4][mr + 8];
                ahi[2] = sAhi[cur][t4 + 4][mr];
                ahi[3] = sAhi[cur][t4 + 4][mr + 8];
                alo[0] = sAlo[cur][t4][mr];
                alo[1] = sAlo[cur][t4][mr + 8];
                alo[2] = sAlo[cur][t4 + 4][mr];
                alo[3] = sAlo[cur][t4 + 4][mr + 8];
                #pragma unroll
                for (int nt = 0; nt < 2; nt++) {
                    mma16(acc[mt][nt], ahi, blo[nt]);
                    mma16(acc[mt][nt], alo, bhi[nt]);
                    mma16(acc[mt][nt], ahi, bhi[nt]);
                }
            }
        }
        if (t + 1 < nT) {
            int nxt = cur ^ 1;
            unsigned h, l;
            bf16_split2(na0.x, na0.y, h, l); sAhi[nxt][lk2 + 0][lrow] = h; sAlo[nxt][lk2 + 0][lrow] = l;
            bf16_split2(na0.z, na0.w, h, l); sAhi[nxt][lk2 + 1][lrow] = h; sAlo[nxt][lk2 + 1][lrow] = l;
            bf16_split2(na1.x, na1.y, h, l); sAhi[nxt][lk2 + 2][lrow] = h; sAlo[nxt][lk2 + 2][lrow] = l;
            bf16_split2(na1.z, na1.w, h, l); sAhi[nxt][lk2 + 3][lrow] = h; sAlo[nxt][lk2 + 3][lrow] = l;
            bf16_split2(nb0.x, nb0.y, h, l); sBhi[nxt][bk2 + 0][brow] = h; sBlo[nxt][bk2 + 0][brow] = l;
            bf16_split2(nb0.z, nb0.w, h, l); sBhi[nxt][bk2 + 1][brow] = h; sBlo[nxt][bk2 + 1][brow] = l;
            __syncthreads();
            cur = nxt;
        }
    }

    // epilogue
    #pragma unroll
    for (int mt = 0; mt < 4; mt++) {
        int r0 = bm + wm * 64 + mt * 16 + g;
        float rsv0 = rowscale ? rowscale[r0] : 1.f;
        float rsv1 = rowscale ? rowscale[r0 + 8] : 1.f;
        #pragma unroll
        for (int nt = 0; nt < 2; nt++) {
            int c0 = bn + wn * 16 + nt * 8 + 2 * t4;
            float bv0 = bias ? bias[c0] : 0.f;
            float bv1 = bias ? bias[c0 + 1] : 0.f;
            float2 w0, w1;
            w0.x = (acc[mt][nt][0] + bv0) * rsv0;
            w0.y = (acc[mt][nt][1] + bv1) * rsv0;
            w1.x = (acc[mt][nt][2] + bv0) * rsv1;
            w1.y = (acc[mt][nt][3] + bv1) * rsv1;
            *(float2*)&C[(size_t)r0 * N + c0] = w0;
            *(float2*)&C[(size_t)(r0 + 8) * N + c0] = w1;
        }
    }
}

// coef[i] = exp(scale) / (||U1_i|| + 1e-4)
__global__ void k_coef(const float* __restrict__ scale) {
    int i = blockIdx.x * 8 + (threadIdx.x >> 5);
    int lane = threadIdx.x & 31;
    const float* u = g_U1 + (size_t)i * NE;
    float s = 0.f;
    #pragma unroll
    for (int k = 0; k < 8; k++) { float v = u[lane + 32 * k]; s += v * v; }
    #pragma unroll
    for (int o = 16; o; o >>= 1) s += __shfl_xor_sync(0xffffffffu, s, o);
    if (lane == 0) g_coef[i] = expf(scale[0]) / (sqrtf(s) + 1e-4f);
}

// argmax over 512 scores per row, first-occurrence tie-break.
__global__ void k_argmax() {
    int i = blockIdx.x * 8 + (threadIdx.x >> 5);
    int lane = threadIdx.x & 31;
    const float* r = g_scores + (size_t)i * NNZ;
    float best = -FLT_MAX; int bi = 0;
    for (int z = lane; z < NNZ; z += 32) {
        float v = r[z];
        if (v > best) { best = v; bi = z; }
    }
    #pragma unroll
    for (int off = 16; off; off >>= 1) {
        float ov = __shfl_down_sync(0xffffffffu, best, off);
        int   oi = __shfl_down_sync(0xffffffffu, bi, off);
        if (ov > best || (ov == best && oi < bi)) { best = ov; bi = oi; }
    }
    if (lane == 0) g_zind[i] = bi;
}

// out[i][j] = G[i][zind[j]]  (256 MB, float4 stores)
__global__ void k_out(float* __restrict__ out) {
    __shared__ float row[NNZ];
    __shared__ int zj[4096];
    int i = blockIdx.y;
    int jb = blockIdx.x * 4096;
    for (int t = threadIdx.x; t < NNZ; t += 256) row[t] = g_G[(size_t)i * NNZ + t];
    for (int t = threadIdx.x; t < 4096; t += 256) zj[t] = g_zind[jb + t];
    __syncthreads();
    float4* op = (float4*)(out + (size_t)i * BATCH + jb);
    #pragma unroll
    for (int k = 0; k < 4; k++) {
        int j4 = (k * 256 + threadIdx.x);
        int j = j4 * 4;
        float4 v;
        v.x = row[zj[j]]; v.y = row[zj[j + 1]];
        v.z = row[zj[j + 2]]; v.w = row[zj[j + 3]];
        op[j4] = v;
    }
}

// ---------------- launcher ----------------
extern "C" void kernel_launch(void* const* d_in, const int* in_sizes, int n_in,
                              void* d_out, int out_size) {
    const int*   s     = (const int*)d_in[0];
    const int*   sp    = (const int*)d_in[1];
    const float* tab   = (const float*)d_in[2];
    const float* cw    = (const float*)d_in[3];
    const float* cb    = (const float*)d_in[4];
    const float* w1a   = (const float*)d_in[5];
    const float* b1a   = (const float*)d_in[6];
    const float* w2a   = (const float*)d_in[7];
    const float* b2a   = (const float*)d_in[8];
    const float* lwa   = (const float*)d_in[9];
    const float* lba   = (const float*)d_in[10];
    const float* w1b   = (const float*)d_in[11];
    const float* b1b   = (const float*)d_in[12];
    const float* w2b   = (const float*)d_in[13];
    const float* b2b   = (const float*)d_in[14];
    const float* lwb   = (const float*)d_in[15];
    const float* lbb   = (const float*)d_in[16];
    const float* zv    = (const float*)d_in[17];
    const float* scale = (const float*)d_in[18];
    float* out = (float*)d_out;

    float *pB1, *pB2, *pU1, *pE2, *pzn, *pscores, *pG, *pcoef;
    cudaGetSymbolAddress((void**)&pB1, g_B1);
    cudaGetSymbolAddress((void**)&pB2, g_B2);
    cudaGetSymbolAddress((void**)&pU1, g_U1);
    cudaGetSymbolAddress((void**)&pE2, g_E2);
    cudaGetSymbolAddress((void**)&pzn, g_zn);
    cudaGetSymbolAddress((void**)&pscores, g_scores);
    cudaGetSymbolAddress((void**)&pG, g_G);
    cudaGetSymbolAddress((void**)&pcoef, g_coef);

    // 1: PE (embn fused)
    k_PE<<<32, 256>>>(cw, tab);
    // 2: R for both phis
    k_R<<<dim3(NP * NDICT, 2), 400>>>(w1a, w1b);
    // 3: C1
    k_C1<<<2, 256>>>(w1a, b1a, cb);
    // 4: stage1 (8 batches/block — measured-good version)
    k_stage1<<<BATCH / 8, 800>>>(s, sp, b1b);
    // 5: conv2 both phis
    k_conv2<<<dim3(BATCH / 8, 2), 200>>>(w2a, b2a, w2b, b2b);
    // 6: combined U1/E2 bgemm (128x64 tiles)
    k_bgemm<<<dim3(NE / 64, BATCH / 128, 2), 256>>>(
        pB1, pB2, lwa, lwb, lba, lbb, nullptr, nullptr, pU1, pE2, K2, NE);
    // 7: zn
    k_zn<<<64, 256>>>(zv);
    // 8: coef
    k_coef<<<1024, 256>>>(scale);
    // 9: combined scores/G bgemm
    k_bgemm<<<dim3(NNZ / 64, BATCH / 128, 2), 256>>>(
        pE2, pU1, pzn, pzn, nullptr, nullptr, nullptr, pcoef,
        pscores, pG, NE, NNZ);
    // 10: argmax
    k_argmax<<<1024, 256>>>();
    // 11: gather-write output
    k_out<<<dim3(2, BATCH), 256>>>(out);
}